// round 3
// baseline (speedup 1.0000x reference)
#include <cuda_runtime.h>

#define D     128
#define TE    128
#define NREL  16
#define NB    8
#define MAXE  600000
#define LDX   129   // padded k-major X tile stride (bank-conflict-free a-reads)

// ---------------- device scratch (no allocations allowed) ----------------
__device__ float g_weights[NREL * D * D];   // [r][i][o]
__device__ float g_wT[D * D];               // w_self transposed: [i][o]
__device__ int   g_counts[NREL];
__device__ int   g_offsets[NREL + 1];
__device__ int   g_cursor[NREL];
__device__ int   g_tileoff[NREL + 1];
__device__ int   g_perm[MAXE];

// ---------------- small helpers: packed f32x2 math ----------------
__device__ __forceinline__ unsigned long long pack_dup(float a) {
    unsigned long long r;
    asm("mov.b64 %0, {%1, %1};" : "=l"(r) : "r"(__float_as_uint(a)));
    return r;
}
__device__ __forceinline__ void fma2(unsigned long long& d,
                                     unsigned long long a,
                                     unsigned long long b) {
    asm("fma.rn.f32x2 %0, %1, %2, %0;" : "+l"(d) : "l"(a), "l"(b));
}
__device__ __forceinline__ float2 unpk(unsigned long long v) {
    unsigned lo, hi;
    asm("mov.b64 {%0, %1}, %2;" : "=r"(lo), "=r"(hi) : "l"(v));
    return make_float2(__uint_as_float(lo), __uint_as_float(hi));
}

// ---------------- prep kernels ----------------
__global__ void k_zero() {
    if (threadIdx.x < NREL) g_counts[threadIdx.x] = 0;
}

// weights[r][i][o] = sum_b coeff[r][b] * bases[b][i][o]
__global__ void k_weights(const float* __restrict__ bases,
                          const float* __restrict__ coeff) {
    __shared__ float sc[NREL * NB];
    if (threadIdx.x < NREL * NB) sc[threadIdx.x] = coeff[threadIdx.x];
    __syncthreads();
    int io = blockIdx.x * blockDim.x + threadIdx.x;   // 0..D*D-1
    float bv[NB];
#pragma unroll
    for (int b = 0; b < NB; b++) bv[b] = bases[b * D * D + io];
#pragma unroll
    for (int r = 0; r < NREL; r++) {
        float s = 0.f;
#pragma unroll
        for (int b = 0; b < NB; b++) s = fmaf(sc[r * NB + b], bv[b], s);
        g_weights[r * D * D + io] = s;
    }
}

// g_wT[i][o] = w_self[o][i]
__global__ void k_wT(const float* __restrict__ w_self) {
    int idx = blockIdx.x * blockDim.x + threadIdx.x;
    int i = idx >> 7, o = idx & 127;
    g_wT[i * D + o] = w_self[o * D + i];
}

__global__ void k_hist(const int* __restrict__ etype, int E) {
    __shared__ int h[NREL];
    if (threadIdx.x < NREL) h[threadIdx.x] = 0;
    __syncthreads();
    int e = blockIdx.x * blockDim.x + threadIdx.x;
    if (e < E) atomicAdd(&h[etype[e] & (NREL - 1)], 1);
    __syncthreads();
    if (threadIdx.x < NREL && h[threadIdx.x])
        atomicAdd(&g_counts[threadIdx.x], h[threadIdx.x]);
}

__global__ void k_scan() {
    int off = 0, toff = 0;
    for (int r = 0; r < NREL; r++) {
        g_offsets[r] = off;
        g_cursor[r]  = off;
        g_tileoff[r] = toff;
        off  += g_counts[r];
        toff += (g_counts[r] + TE - 1) / TE;
    }
    g_offsets[NREL] = off;
    g_tileoff[NREL] = toff;
}

// block-aggregated counting-sort scatter: perm groups edges by relation
__global__ void k_perm(const int* __restrict__ etype, int E) {
    __shared__ int h[NREL];
    __shared__ int base[NREL];
    if (threadIdx.x < NREL) h[threadIdx.x] = 0;
    __syncthreads();
    int e = blockIdx.x * blockDim.x + threadIdx.x;
    int r = 0, loc = 0;
    bool valid = (e < E);
    if (valid) {
        r = etype[e] & (NREL - 1);
        loc = atomicAdd(&h[r], 1);
    }
    __syncthreads();
    if (threadIdx.x < NREL) {
        int c = h[threadIdx.x];
        base[threadIdx.x] = c ? atomicAdd(&g_cursor[threadIdx.x], c) : 0;
    }
    __syncthreads();
    if (valid) g_perm[base[r] + loc] = e;
}

// ---------------- self-loop GEMM: out = x @ w_selfT (initializes out) ----------------
__global__ void __launch_bounds__(256, 1)
k_self(const float* __restrict__ x, float* __restrict__ out, int N) {
    extern __shared__ float smem[];
    float* sW  = smem;            // [k][o]  D*D
    float* sXt = smem + D * D;    // [k][n]  D*LDX, padded

    int n0 = blockIdx.x * TE;

    const float4* Wg = (const float4*)g_wT;
    float4* sW4 = (float4*)sW;
#pragma unroll
    for (int i = threadIdx.x; i < D * D / 4; i += 256) sW4[i] = Wg[i];

    int warp = threadIdx.x >> 5, lane = threadIdx.x & 31;
#pragma unroll
    for (int e = warp; e < TE; e += 8) {
        int n = n0 + e;
        float4 v = make_float4(0.f, 0.f, 0.f, 0.f);
        if (n < N) v = ((const float4*)(x + (long long)n * D))[lane];
        int k0 = lane << 2;
        sXt[(k0 + 0) * LDX + e] = v.x;
        sXt[(k0 + 1) * LDX + e] = v.y;
        sXt[(k0 + 2) * LDX + e] = v.z;
        sXt[(k0 + 3) * LDX + e] = v.w;
    }
    __syncthreads();

    int ty = threadIdx.x >> 4, tx = threadIdx.x & 15;
    unsigned long long acc[8][4];
#pragma unroll
    for (int i = 0; i < 8; i++)
#pragma unroll
        for (int p = 0; p < 4; p++) acc[i][p] = 0ULL;

    const float* aBase = sXt + ty * 8;
    const float* bBase = sW + tx * 8;
#pragma unroll 2
    for (int k = 0; k < D; k++) {
        const float* ar = aBase + k * LDX;
        unsigned long long a2[8];
#pragma unroll
        for (int i = 0; i < 8; i++) a2[i] = pack_dup(ar[i]);
        const ulonglong2* bp = (const ulonglong2*)(bBase + k * D);
        ulonglong2 u0 = bp[0];
        ulonglong2 u1 = bp[1];
        unsigned long long b2[4] = {u0.x, u0.y, u1.x, u1.y};
#pragma unroll
        for (int i = 0; i < 8; i++)
#pragma unroll
            for (int p = 0; p < 4; p++) fma2(acc[i][p], a2[i], b2[p]);
    }

#pragma unroll
    for (int i = 0; i < 8; i++) {
        int n = n0 + ty * 8 + i;
        if (n < N) {
            float* dst = out + (long long)n * D + tx * 8;
            float2 p0 = unpk(acc[i][0]), p1 = unpk(acc[i][1]);
            float2 p2 = unpk(acc[i][2]), p3 = unpk(acc[i][3]);
            *(float4*)dst       = make_float4(p0.x, p0.y, p1.x, p1.y);
            *(float4*)(dst + 4) = make_float4(p2.x, p2.y, p3.x, p3.y);
        }
    }
}

// ---------------- edge grouped GEMM + atomic scatter ----------------
__global__ void __launch_bounds__(256, 1)
k_edge(const float* __restrict__ x, const int* __restrict__ ei,
       float* __restrict__ out, int E) {
    __shared__ int s_toff[NREL + 1];
    __shared__ int s_off[NREL + 1];
    __shared__ int s_row[TE];
    extern __shared__ float smem[];
    float* sW  = smem;            // W_r [k][o]
    float* sXt = smem + D * D;    // gathered X, [k][e] padded

    if (threadIdx.x < NREL + 1) {
        s_toff[threadIdx.x] = g_tileoff[threadIdx.x];
        s_off[threadIdx.x]  = g_offsets[threadIdx.x];
    }
    __syncthreads();

    int b = blockIdx.x;
    if (b >= s_toff[NREL]) return;
    int r = 0;
#pragma unroll
    for (int i = 1; i < NREL; i++) if (s_toff[i] <= b) r = i;
    int e_begin = s_off[r] + (b - s_toff[r]) * TE;
    int ne = min(s_off[r + 1] - e_begin, TE);

    // stage W_r (64 KB, L2-resident)
    const float4* Wg = (const float4*)(g_weights + r * D * D);
    float4* sW4 = (float4*)sW;
#pragma unroll
    for (int i = threadIdx.x; i < D * D / 4; i += 256) sW4[i] = Wg[i];

    // gather source rows (transposed into [k][e])
    int warp = threadIdx.x >> 5, lane = threadIdx.x & 31;
#pragma unroll
    for (int e = warp; e < TE; e += 8) {
        float4 v = make_float4(0.f, 0.f, 0.f, 0.f);
        if (e < ne) {
            int idx = g_perm[e_begin + e];
            int c = ei[E + idx];                  // col = edge_index[1][idx]
            v = ((const float4*)(x + (long long)c * D))[lane];
            if (lane == 0) s_row[e] = ei[idx];    // row = edge_index[0][idx]
        } else if (lane == 0) {
            s_row[e] = -1;
        }
        int k0 = lane << 2;
        sXt[(k0 + 0) * LDX + e] = v.x;
        sXt[(k0 + 1) * LDX + e] = v.y;
        sXt[(k0 + 2) * LDX + e] = v.z;
        sXt[(k0 + 3) * LDX + e] = v.w;
    }
    __syncthreads();

    int ty = threadIdx.x >> 4, tx = threadIdx.x & 15;
    unsigned long long acc[8][4];
#pragma unroll
    for (int i = 0; i < 8; i++)
#pragma unroll
        for (int p = 0; p < 4; p++) acc[i][p] = 0ULL;

    const float* aBase = sXt + ty * 8;
    const float* bBase = sW + tx * 8;
#pragma unroll 2
    for (int k = 0; k < D; k++) {
        const float* ar = aBase + k * LDX;
        unsigned long long a2[8];
#pragma unroll
        for (int i = 0; i < 8; i++) a2[i] = pack_dup(ar[i]);
        const ulonglong2* bp = (const ulonglong2*)(bBase + k * D);
        ulonglong2 u0 = bp[0];
        ulonglong2 u1 = bp[1];
        unsigned long long b2[4] = {u0.x, u0.y, u1.x, u1.y};
#pragma unroll
        for (int i = 0; i < 8; i++)
#pragma unroll
            for (int p = 0; p < 4; p++) fma2(acc[i][p], a2[i], b2[p]);
    }

    // scatter-add with vector atomics (sm_90+ float4 RED)
#pragma unroll
    for (int i = 0; i < 8; i++) {
        int rr = s_row[ty * 8 + i];
        if (rr >= 0) {
            float* dst = out + (long long)rr * D + tx * 8;
            float2 p0 = unpk(acc[i][0]), p1 = unpk(acc[i][1]);
            float2 p2 = unpk(acc[i][2]), p3 = unpk(acc[i][3]);
            atomicAdd((float4*)dst,       make_float4(p0.x, p0.y, p1.x, p1.y));
            atomicAdd((float4*)(dst + 4), make_float4(p2.x, p2.y, p3.x, p3.y));
        }
    }
}

// ---------------- launcher ----------------
extern "C" void kernel_launch(void* const* d_in, const int* in_sizes, int n_in,
                              void* d_out, int out_size) {
    const float* x     = (const float*)d_in[0];
    const int*   ei    = (const int*)d_in[1];     // int32: jax demotes int64
    const int*   et    = (const int*)d_in[2];     // int32
    const float* bases = (const float*)d_in[3];
    const float* coeff = (const float*)d_in[4];
    const float* wself = (const float*)d_in[5];
    float* out = (float*)d_out;

    int N = in_sizes[0] / D;
    int E = in_sizes[2];
    if (E > MAXE) E = MAXE;

    size_t smem = (size_t)(D * D + D * LDX) * sizeof(float);  // ~128.5 KB
    cudaFuncSetAttribute(k_edge, cudaFuncAttributeMaxDynamicSharedMemorySize, (int)smem);
    cudaFuncSetAttribute(k_self, cudaFuncAttributeMaxDynamicSharedMemorySize, (int)smem);

    k_zero<<<1, 32>>>();
    k_weights<<<(D * D) / 256, 256>>>(bases, coeff);
    k_wT<<<(D * D) / 256, 256>>>(wself);

    int gb = (E + 255) / 256;
    k_hist<<<gb, 256>>>(et, E);
    k_scan<<<1, 1>>>();
    k_perm<<<gb, 256>>>(et, E);

    k_self<<<(N + TE - 1) / TE, 256, smem>>>(x, out, N);

    int tilesUB = (E + TE - 1) / TE + NREL;
    k_edge<<<tilesUB, 256, smem>>>(x, ei, out, E);
}

// round 11
// speedup vs baseline: 2.0762x; 2.0762x over previous
#include <cuda_runtime.h>
#include <cuda_bf16.h>
#include <cstdint>

#define D     128
#define TE    128
#define NREL  16
#define NB    8
#define MAXE  600000

#define LDT   136                 // padded tile row, bf16 elems
#define LDTB  (LDT * 2)           // 272 bytes
#define TILE_SH (128 * LDT)       // ushorts per panel (17408)
#define PANEL_B (TILE_SH * 2)     // 34816 bytes

// dynamic smem offsets
#define A_HI  0
#define A_LO  (PANEL_B)
#define B_HI  (2 * PANEL_B)
#define B_LO  (3 * PANEL_B)
#define SMEM_DYN (4 * PANEL_B)    // 139264 B

// ---------------- device scratch ----------------
__device__ __align__(16) unsigned short g_Bhi[NREL * TILE_SH]; // W_r^T [o][k] hi, padded
__device__ __align__(16) unsigned short g_Blo[NREL * TILE_SH];
__device__ __align__(16) unsigned short g_Shi[TILE_SH];        // w_self [o][k] hi
__device__ __align__(16) unsigned short g_Slo[TILE_SH];
__device__ int g_counts[NREL];
__device__ int g_offsets[NREL + 1];
__device__ int g_cursor[NREL];
__device__ int g_tileoff[NREL + 1];
__device__ int g_perm[MAXE];
__device__ int g_ticket;

// ---------------- PTX helpers (baseline ISA only) ----------------
__device__ __forceinline__ uint32_t smem_u32(const void* p) {
    uint32_t a;
    asm("{ .reg .u64 t; cvta.to.shared.u64 t, %1; cvt.u32.u64 %0, t; }" : "=r"(a) : "l"(p));
    return a;
}
__device__ __forceinline__ void ldsm4(uint32_t* r, uint32_t addr) {
    asm volatile("ldmatrix.sync.aligned.m8n8.x4.shared.b16 {%0,%1,%2,%3}, [%4];"
                 : "=r"(r[0]), "=r"(r[1]), "=r"(r[2]), "=r"(r[3]) : "r"(addr));
}
__device__ __forceinline__ void mma16816(float* c, const uint32_t* a,
                                         uint32_t b0, uint32_t b1) {
    asm volatile(
        "mma.sync.aligned.m16n8k16.row.col.f32.bf16.bf16.f32 "
        "{%0,%1,%2,%3}, {%4,%5,%6,%7}, {%8,%9}, {%0,%1,%2,%3};"
        : "+f"(c[0]), "+f"(c[1]), "+f"(c[2]), "+f"(c[3])
        : "r"(a[0]), "r"(a[1]), "r"(a[2]), "r"(a[3]), "r"(b0), "r"(b1));
}
__device__ __forceinline__ uint32_t pk2(float a, float b) {
    __nv_bfloat162 t = __floats2bfloat162_rn(a, b);
    return *reinterpret_cast<uint32_t*>(&t);
}

// ---------------- prep kernels ----------------
__global__ void k_zero() {
    if (threadIdx.x < NREL) g_counts[threadIdx.x] = 0;
    if (threadIdx.x == 0) g_ticket = 0;
}

// g_B*[r][n=o][k=i] = split of sum_b coeff[r][b]*bases[b][i][o]
__global__ void k_wprep(const float* __restrict__ bases,
                        const float* __restrict__ coeff) {
    int idx = blockIdx.x * blockDim.x + threadIdx.x;  // NREL*128*128
    int r = idx >> 14;
    int n = (idx >> 7) & 127;   // o
    int k = idx & 127;          // i
    float s = 0.f;
#pragma unroll
    for (int b = 0; b < NB; b++)
        s = fmaf(__ldg(&coeff[r * NB + b]), __ldg(&bases[b * D * D + k * D + n]), s);
    __nv_bfloat16 hi = __float2bfloat16_rn(s);
    __nv_bfloat16 lo = __float2bfloat16_rn(s - __bfloat162float(hi));
    int o = r * TILE_SH + n * LDT + k;
    g_Bhi[o] = *reinterpret_cast<unsigned short*>(&hi);
    g_Blo[o] = *reinterpret_cast<unsigned short*>(&lo);
}

// self: B^T[n=o][k=i] = w_self[o][i] (row-major already)
__global__ void k_sprep(const float* __restrict__ w_self) {
    int idx = blockIdx.x * blockDim.x + threadIdx.x;  // 128*128
    int n = idx >> 7, k = idx & 127;
    float s = w_self[n * D + k];
    __nv_bfloat16 hi = __float2bfloat16_rn(s);
    __nv_bfloat16 lo = __float2bfloat16_rn(s - __bfloat162float(hi));
    g_Shi[n * LDT + k] = *reinterpret_cast<unsigned short*>(&hi);
    g_Slo[n * LDT + k] = *reinterpret_cast<unsigned short*>(&lo);
}

__global__ void k_hist(const int* __restrict__ etype, int E) {
    __shared__ int h[NREL];
    if (threadIdx.x < NREL) h[threadIdx.x] = 0;
    __syncthreads();
    int e = blockIdx.x * blockDim.x + threadIdx.x;
    if (e < E) atomicAdd(&h[etype[e] & (NREL - 1)], 1);
    __syncthreads();
    if (threadIdx.x < NREL && h[threadIdx.x])
        atomicAdd(&g_counts[threadIdx.x], h[threadIdx.x]);
}

__global__ void k_scan() {
    int off = 0, toff = 0;
    for (int r = 0; r < NREL; r++) {
        g_offsets[r] = off;
        g_cursor[r]  = off;
        g_tileoff[r] = toff;
        off  += g_counts[r];
        toff += (g_counts[r] + TE - 1) / TE;
    }
    g_offsets[NREL] = off;
    g_tileoff[NREL] = toff;
}

__global__ void k_perm(const int* __restrict__ etype, int E) {
    __shared__ int h[NREL];
    __shared__ int base[NREL];
    if (threadIdx.x < NREL) h[threadIdx.x] = 0;
    __syncthreads();
    int e = blockIdx.x * blockDim.x + threadIdx.x;
    int r = 0, loc = 0;
    bool valid = (e < E);
    if (valid) {
        r = etype[e] & (NREL - 1);
        loc = atomicAdd(&h[r], 1);
    }
    __syncthreads();
    if (threadIdx.x < NREL) {
        int c = h[threadIdx.x];
        base[threadIdx.x] = c ? atomicAdd(&g_cursor[threadIdx.x], c) : 0;
    }
    __syncthreads();
    if (valid) g_perm[base[r] + loc] = e;
}

// ---------------- shared warp-level mma core ----------------
// A tiles (hi/lo) at dsm+A_HI/A_LO: [128 m][128 k] bf16, row stride LDTB.
// B tiles (hi/lo) at dsm+B_HI/B_LO: [128 n][128 k] bf16 (col-major B), stride LDTB.
// Warp wid computes m-rows [16*wid, 16*wid+16) x all 128 n into acc[16][4].
__device__ __forceinline__ void warp_mma(const char* dsm, int wid, int lane,
                                         float acc[16][4]) {
#pragma unroll
    for (int t = 0; t < 16; t++)
#pragma unroll
        for (int q = 0; q < 4; q++) acc[t][q] = 0.f;

    uint32_t sAh = smem_u32(dsm + A_HI);
    uint32_t sAl = smem_u32(dsm + A_LO);
    uint32_t sBh = smem_u32(dsm + B_HI);
    uint32_t sBl = smem_u32(dsm + B_LO);

    int m0 = wid * 16;
    // A ldmatrix.x4 lane address: quadrants m0..m3 = (r0-7,k0-7),(r8-15,k0-7),(r0-7,k8-15),(r8-15,k8-15)
    uint32_t arow = (uint32_t)(m0 + (lane & 7) + 8 * ((lane >> 3) & 1)) * LDTB
                  + ((lane >> 4) << 4);

    uint32_t ahi[8][4], alo[8][4];
#pragma unroll
    for (int k = 0; k < 8; k++) {
        ldsm4(ahi[k], sAh + arow + k * 32);
        ldsm4(alo[k], sAl + arow + k * 32);
    }

    // B ldmatrix.x4 serves 2 n-tiles x 2 k-halves: groups g=lane>>3:
    // g0: ntileA,k0-7  g1: ntileA,k8-15  g2: ntileB,k0-7  g3: ntileB,k8-15
    int g = lane >> 3, rr = lane & 7;
    uint32_t brow = (uint32_t)(((g >> 1) * 8 + rr)) * LDTB + (uint32_t)((g & 1) << 4);

#pragma unroll
    for (int p = 0; p < 8; p++) {
        uint32_t bph = sBh + (uint32_t)(p * 16) * LDTB + brow;
        uint32_t bpl = sBl + (uint32_t)(p * 16) * LDTB + brow;
#pragma unroll
        for (int k = 0; k < 8; k++) {
            uint32_t bh[4], bl[4];
            ldsm4(bh, bph + k * 32);
            ldsm4(bl, bpl + k * 32);
            mma16816(acc[2 * p],     ahi[k], bh[0], bh[1]);
            mma16816(acc[2 * p],     alo[k], bh[0], bh[1]);
            mma16816(acc[2 * p],     ahi[k], bl[0], bl[1]);
            mma16816(acc[2 * p + 1], ahi[k], bh[2], bh[3]);
            mma16816(acc[2 * p + 1], alo[k], bh[2], bh[3]);
            mma16816(acc[2 * p + 1], ahi[k], bl[2], bl[3]);
        }
    }
}

// convert one x-row (64 floats at src, k-half 'half') into hi/lo bf16 smem row e
__device__ __forceinline__ void cvt_row(char* dsm, int e, int half,
                                        const float4* __restrict__ src4) {
    char* ah = dsm + A_HI + e * LDTB + half * 128;
    char* al = dsm + A_LO + e * LDTB + half * 128;
#pragma unroll
    for (int j = 0; j < 8; j++) {
        float4 u = src4[2 * j];
        float4 v = src4[2 * j + 1];
        float f[8] = {u.x, u.y, u.z, u.w, v.x, v.y, v.z, v.w};
        float l[8];
#pragma unroll
        for (int q = 0; q < 8; q++) {
            float h = __bfloat162float(__float2bfloat16_rn(f[q]));
            l[q] = f[q] - h;
        }
        uint4 H = make_uint4(pk2(f[0], f[1]), pk2(f[2], f[3]), pk2(f[4], f[5]), pk2(f[6], f[7]));
        uint4 L = make_uint4(pk2(l[0], l[1]), pk2(l[2], l[3]), pk2(l[4], l[5]), pk2(l[6], l[7]));
        *(uint4*)(ah + j * 16) = H;
        *(uint4*)(al + j * 16) = L;
    }
}

// ---------------- self-loop GEMM: out = x @ w_selfT (initializes out) ----------------
__global__ void __launch_bounds__(256, 1)
k_self(const float* __restrict__ x, float* __restrict__ out, int N) {
    extern __shared__ char dsm[];
    int tid = threadIdx.x;
    int wid = tid >> 5, lane = tid & 31;
    int n0 = blockIdx.x * TE;

    // stage B (w_self hi/lo)
    {
        const uint4* shi = (const uint4*)g_Shi;
        const uint4* slo = (const uint4*)g_Slo;
        uint4* dhi = (uint4*)(dsm + B_HI);
        uint4* dlo = (uint4*)(dsm + B_LO);
#pragma unroll
        for (int i = tid; i < PANEL_B / 16; i += 256) {
            dhi[i] = shi[i];
            dlo[i] = slo[i];
        }
    }
    // gather + convert A
    int e = tid & 127, half = tid >> 7;
    int n = n0 + e;
    if (n < N)
        cvt_row(dsm, e, half, (const float4*)(x + (long long)n * D + half * 64));
    __syncthreads();

    float acc[16][4];
    warp_mma(dsm, wid, lane, acc);

    int ra = n0 + wid * 16 + (lane >> 2);
    int rb = ra + 8;
    int cb = (lane & 3) * 2;
#pragma unroll
    for (int t = 0; t < 16; t++) {
        if (ra < N) *(float2*)(out + (long long)ra * D + t * 8 + cb) = make_float2(acc[t][0], acc[t][1]);
        if (rb < N) *(float2*)(out + (long long)rb * D + t * 8 + cb) = make_float2(acc[t][2], acc[t][3]);
    }
}

// ---------------- persistent edge grouped GEMM + atomic scatter ----------------
__global__ void __launch_bounds__(256, 1)
k_edge(const float* __restrict__ x, const int* __restrict__ ei,
       float* __restrict__ out, int E) {
    __shared__ int s_toff[NREL + 1];
    __shared__ int s_off[NREL + 1];
    __shared__ int s_row[TE];
    __shared__ int s_tile;
    extern __shared__ char dsm[];

    int tid = threadIdx.x;
    int wid = tid >> 5, lane = tid & 31;

    if (tid < NREL + 1) {
        s_toff[tid] = g_tileoff[tid];
        s_off[tid]  = g_offsets[tid];
    }
    __syncthreads();
    int n_tiles = s_toff[NREL];

    int prev_r = -1;
    int e = tid & 127, half = tid >> 7;

    for (;;) {
        if (tid == 0) s_tile = atomicAdd(&g_ticket, 1);
        __syncthreads();
        int t = s_tile;
        if (t >= n_tiles) break;

        int r = 0;
#pragma unroll
        for (int i = 1; i < NREL; i++) if (s_toff[i] <= t) r = i;
        int e_begin = s_off[r] + (t - s_toff[r]) * TE;
        int ne = min(s_off[r + 1] - e_begin, TE);

        if (r != prev_r) {
            const uint4* shi = (const uint4*)(g_Bhi + r * TILE_SH);
            const uint4* slo = (const uint4*)(g_Blo + r * TILE_SH);
            uint4* dhi = (uint4*)(dsm + B_HI);
            uint4* dlo = (uint4*)(dsm + B_LO);
#pragma unroll
            for (int i = tid; i < PANEL_B / 16; i += 256) {
                dhi[i] = shi[i];
                dlo[i] = slo[i];
            }
            prev_r = r;
        }

        if (e < ne) {
            int idx = g_perm[e_begin + e];
            int col = ei[E + idx];
            if (half == 0) s_row[e] = ei[idx];
            cvt_row(dsm, e, half, (const float4*)(x + (long long)col * D + half * 64));
        } else if (half == 0) {
            s_row[e] = -1;
        }
        __syncthreads();

        float acc[16][4];
        warp_mma(dsm, wid, lane, acc);

        int ra = s_row[wid * 16 + (lane >> 2)];
        int rb = s_row[wid * 16 + (lane >> 2) + 8];
        int cb = (lane & 3) * 2;
#pragma unroll
        for (int t2 = 0; t2 < 16; t2++) {
            if (ra >= 0)
                atomicAdd((float2*)(out + (long long)ra * D + t2 * 8 + cb),
                          make_float2(acc[t2][0], acc[t2][1]));
            if (rb >= 0)
                atomicAdd((float2*)(out + (long long)rb * D + t2 * 8 + cb),
                          make_float2(acc[t2][2], acc[t2][3]));
        }
        __syncthreads();   // protect s_row/smem tiles before next iteration's writes
    }
}

// ---------------- launcher ----------------
extern "C" void kernel_launch(void* const* d_in, const int* in_sizes, int n_in,
                              void* d_out, int out_size) {
    const float* x     = (const float*)d_in[0];
    const int*   ei    = (const int*)d_in[1];
    const int*   et    = (const int*)d_in[2];
    const float* bases = (const float*)d_in[3];
    const float* coeff = (const float*)d_in[4];
    const float* wself = (const float*)d_in[5];
    float* out = (float*)d_out;

    int N = in_sizes[0] / D;
    int E = in_sizes[2];
    if (E > MAXE) E = MAXE;

    int dev = 0, nsm = 148;
    cudaGetDevice(&dev);
    cudaDeviceGetAttribute(&nsm, cudaDevAttrMultiProcessorCount, dev);

    cudaFuncSetAttribute(k_self, cudaFuncAttributeMaxDynamicSharedMemorySize, SMEM_DYN);
    cudaFuncSetAttribute(k_edge, cudaFuncAttributeMaxDynamicSharedMemorySize, SMEM_DYN);

    k_zero<<<1, 32>>>();
    k_wprep<<<(NREL * D * D) / 256, 256>>>(bases, coeff);
    k_sprep<<<(D * D) / 256, 256>>>(wself);

    int gb = (E + 255) / 256;
    k_hist<<<gb, 256>>>(et, E);
    k_scan<<<1, 1>>>();
    k_perm<<<gb, 256>>>(et, E);

    k_self<<<(N + TE - 1) / TE, 256, SMEM_DYN>>>(x, out, N);
    k_edge<<<nsm, 256, SMEM_DYN>>>(x, ei, out, E);
}

// round 13
// speedup vs baseline: 2.2637x; 1.0903x over previous
#include <cuda_runtime.h>
#include <cuda_bf16.h>
#include <cstdint>

#define D     128
#define TE    128
#define NREL  16
#define NB    8
#define MAXE  600000
#define MAXN  100000

#define LDT   136                 // padded tile row, bf16 elems
#define LDTB  (LDT * 2)           // 272 bytes
#define TILE_SH (128 * LDT)       // ushorts per panel
#define PANEL_B (TILE_SH * 2)     // 34816 bytes

// dynamic smem layout: A double-buffered (hi,lo per buffer), then B (hi,lo)
#define ABUF(p) ((p) * 2 * PANEL_B)           // hi at +0, lo at +PANEL_B
#define BOFS    (4 * PANEL_B)                  // 139264
#define SMEM_DYN (6 * PANEL_B)                 // 208896 B

// ---------------- device scratch ----------------
__device__ __align__(16) unsigned short g_xhi[MAXN * D];       // x hi bf16
__device__ __align__(16) unsigned short g_xlo[MAXN * D];       // x lo bf16
__device__ __align__(16) unsigned short g_Bhi[NREL * TILE_SH]; // W_r^T [o][k] hi, padded
__device__ __align__(16) unsigned short g_Blo[NREL * TILE_SH];
__device__ __align__(16) unsigned short g_Shi[TILE_SH];        // w_self [o][k] hi
__device__ __align__(16) unsigned short g_Slo[TILE_SH];
__device__ int g_counts[NREL];
__device__ int g_offsets[NREL + 1];
__device__ int g_cursor[NREL];
__device__ int g_tileoff[NREL + 1];
__device__ int g_perm[MAXE];
__device__ int g_ticket;

// ---------------- PTX helpers (baseline ISA only) ----------------
__device__ __forceinline__ uint32_t smem_u32(const void* p) {
    uint32_t a;
    asm("{ .reg .u64 t; cvta.to.shared.u64 t, %1; cvt.u32.u64 %0, t; }" : "=r"(a) : "l"(p));
    return a;
}
__device__ __forceinline__ void ldsm4(uint32_t* r, uint32_t addr) {
    asm volatile("ldmatrix.sync.aligned.m8n8.x4.shared.b16 {%0,%1,%2,%3}, [%4];"
                 : "=r"(r[0]), "=r"(r[1]), "=r"(r[2]), "=r"(r[3]) : "r"(addr));
}
__device__ __forceinline__ void mma16816(float* c, const uint32_t* a,
                                         uint32_t b0, uint32_t b1) {
    asm volatile(
        "mma.sync.aligned.m16n8k16.row.col.f32.bf16.bf16.f32 "
        "{%0,%1,%2,%3}, {%4,%5,%6,%7}, {%8,%9}, {%0,%1,%2,%3};"
        : "+f"(c[0]), "+f"(c[1]), "+f"(c[2]), "+f"(c[3])
        : "r"(a[0]), "r"(a[1]), "r"(a[2]), "r"(a[3]), "r"(b0), "r"(b1));
}
__device__ __forceinline__ uint32_t pk2(float a, float b) {
    __nv_bfloat162 t = __floats2bfloat162_rn(a, b);
    return *reinterpret_cast<uint32_t*>(&t);
}
__device__ __forceinline__ void cp16(uint32_t saddr, const void* gptr) {
    asm volatile("cp.async.cg.shared.global [%0], [%1], 16;"
                 :: "r"(saddr), "l"((uint64_t)__cvta_generic_to_global(gptr)) : "memory");
}
__device__ __forceinline__ void cp_commit() {
    asm volatile("cp.async.commit_group;" ::: "memory");
}
__device__ __forceinline__ void cp_wait0() {
    asm volatile("cp.async.wait_group 0;" ::: "memory");
}

// ---------------- prep kernels ----------------
// x -> bf16 hi/lo split, once per node
__global__ void k_xprep(const float* __restrict__ x, int n4) {
    int g = blockIdx.x * blockDim.x + threadIdx.x;
    if (g >= n4) return;
    float4 v = ((const float4*)x)[g];
    float hx = __bfloat162float(__float2bfloat16_rn(v.x));
    float hy = __bfloat162float(__float2bfloat16_rn(v.y));
    float hz = __bfloat162float(__float2bfloat16_rn(v.z));
    float hw = __bfloat162float(__float2bfloat16_rn(v.w));
    ((uint2*)g_xhi)[g] = make_uint2(pk2(v.x, v.y), pk2(v.z, v.w));
    ((uint2*)g_xlo)[g] = make_uint2(pk2(v.x - hx, v.y - hy), pk2(v.z - hz, v.w - hw));
}

// g_B*[r][n=o][k=i] = split of sum_b coeff[r][b]*bases[b][i][o]
__global__ void k_wprep(const float* __restrict__ bases,
                        const float* __restrict__ coeff) {
    int idx = blockIdx.x * blockDim.x + threadIdx.x;
    int r = idx >> 14;
    int n = (idx >> 7) & 127;
    int k = idx & 127;
    float s = 0.f;
#pragma unroll
    for (int b = 0; b < NB; b++)
        s = fmaf(__ldg(&coeff[r * NB + b]), __ldg(&bases[b * D * D + k * D + n]), s);
    __nv_bfloat16 hi = __float2bfloat16_rn(s);
    __nv_bfloat16 lo = __float2bfloat16_rn(s - __bfloat162float(hi));
    int o = r * TILE_SH + n * LDT + k;
    g_Bhi[o] = *reinterpret_cast<unsigned short*>(&hi);
    g_Blo[o] = *reinterpret_cast<unsigned short*>(&lo);
}

// self weights + zero counters
__global__ void k_sprep(const float* __restrict__ w_self) {
    int idx = blockIdx.x * blockDim.x + threadIdx.x;
    if (idx < NREL) g_counts[idx] = 0;
    if (idx == 0) g_ticket = 0;
    int n = idx >> 7, k = idx & 127;
    float s = w_self[n * D + k];
    __nv_bfloat16 hi = __float2bfloat16_rn(s);
    __nv_bfloat16 lo = __float2bfloat16_rn(s - __bfloat162float(hi));
    g_Shi[n * LDT + k] = *reinterpret_cast<unsigned short*>(&hi);
    g_Slo[n * LDT + k] = *reinterpret_cast<unsigned short*>(&lo);
}

__global__ void k_hist(const int* __restrict__ etype, int E) {
    __shared__ int h[NREL];
    if (threadIdx.x < NREL) h[threadIdx.x] = 0;
    __syncthreads();
    int e = blockIdx.x * blockDim.x + threadIdx.x;
    if (e < E) atomicAdd(&h[etype[e] & (NREL - 1)], 1);
    __syncthreads();
    if (threadIdx.x < NREL && h[threadIdx.x])
        atomicAdd(&g_counts[threadIdx.x], h[threadIdx.x]);
}

__global__ void k_scan() {
    int off = 0, toff = 0;
    for (int r = 0; r < NREL; r++) {
        g_offsets[r] = off;
        g_cursor[r]  = off;
        g_tileoff[r] = toff;
        off  += g_counts[r];
        toff += (g_counts[r] + TE - 1) / TE;
    }
    g_offsets[NREL] = off;
    g_tileoff[NREL] = toff;
}

__global__ void k_perm(const int* __restrict__ etype, int E) {
    __shared__ int h[NREL];
    __shared__ int base[NREL];
    if (threadIdx.x < NREL) h[threadIdx.x] = 0;
    __syncthreads();
    int e = blockIdx.x * blockDim.x + threadIdx.x;
    int r = 0, loc = 0;
    bool valid = (e < E);
    if (valid) {
        r = etype[e] & (NREL - 1);
        loc = atomicAdd(&h[r], 1);
    }
    __syncthreads();
    if (threadIdx.x < NREL) {
        int c = h[threadIdx.x];
        base[threadIdx.x] = c ? atomicAdd(&g_cursor[threadIdx.x], c) : 0;
    }
    __syncthreads();
    if (valid) g_perm[base[r] + loc] = e;
}

// ---------------- warp-level mma core (unchanged addressing, verified) ----------------
__device__ __forceinline__ void warp_mma(const char* dsm, int aofs, int wid, int lane,
                                         float acc[16][4]) {
#pragma unroll
    for (int t = 0; t < 16; t++)
#pragma unroll
        for (int q = 0; q < 4; q++) acc[t][q] = 0.f;

    uint32_t sAh = smem_u32(dsm + aofs);
    uint32_t sAl = sAh + PANEL_B;
    uint32_t sBh = smem_u32(dsm + BOFS);
    uint32_t sBl = sBh + PANEL_B;

    int m0 = wid * 16;
    uint32_t arow = (uint32_t)(m0 + (lane & 7) + 8 * ((lane >> 3) & 1)) * LDTB
                  + ((lane >> 4) << 4);

    uint32_t ahi[8][4], alo[8][4];
#pragma unroll
    for (int k = 0; k < 8; k++) {
        ldsm4(ahi[k], sAh + arow + k * 32);
        ldsm4(alo[k], sAl + arow + k * 32);
    }

    int g = lane >> 3, rr = lane & 7;
    uint32_t brow = (uint32_t)(((g >> 1) * 8 + rr)) * LDTB + (uint32_t)((g & 1) << 4);

#pragma unroll
    for (int p = 0; p < 8; p++) {
        uint32_t bph = sBh + (uint32_t)(p * 16) * LDTB + brow;
        uint32_t bpl = sBl + (uint32_t)(p * 16) * LDTB + brow;
#pragma unroll
        for (int k = 0; k < 8; k++) {
            uint32_t bh[4], bl[4];
            ldsm4(bh, bph + k * 32);
            ldsm4(bl, bpl + k * 32);
            mma16816(acc[2 * p],     ahi[k], bh[0], bh[1]);
            mma16816(acc[2 * p],     alo[k], bh[0], bh[1]);
            mma16816(acc[2 * p],     ahi[k], bl[0], bl[1]);
            mma16816(acc[2 * p + 1], ahi[k], bh[2], bh[3]);
            mma16816(acc[2 * p + 1], alo[k], bh[2], bh[3]);
            mma16816(acc[2 * p + 1], ahi[k], bl[2], bl[3]);
        }
    }
}

// issue async copy of one edge row half (hi+lo) from pre-converted x
__device__ __forceinline__ void issue_gather(char* dsm, int bufofs, int e, int half, int col) {
    if (col < 0) return;
    const unsigned short* sh = g_xhi + (long long)col * D + half * 64;
    const unsigned short* sl = g_xlo + (long long)col * D + half * 64;
    uint32_t dh = smem_u32(dsm + bufofs + e * LDTB + half * 128);
    uint32_t dl = dh + PANEL_B;
#pragma unroll
    for (int j = 0; j < 8; j++) {
        cp16(dh + j * 16, sh + j * 8);
        cp16(dl + j * 16, sl + j * 8);
    }
}

__device__ __forceinline__ void resolve_tile(const int* s_toff, const int* s_off,
                                             int t, int n_tiles,
                                             int& r, int& e0, int& ne) {
    r = 0; e0 = 0; ne = 0;
    if (t >= n_tiles) return;
#pragma unroll
    for (int i = 1; i < NREL; i++) if (s_toff[i] <= t) r = i;
    e0 = s_off[r] + (t - s_toff[r]) * TE;
    ne = min(s_off[r + 1] - e0, TE);
}

__device__ __forceinline__ void load_edge(const int* __restrict__ ei, int E,
                                          int e0, int ne, int e,
                                          int& col, int& row) {
    col = -1; row = -1;
    if (e < ne) {
        int idx = __ldg(&g_perm[e0 + e]);
        col = __ldg(&ei[E + idx]);
        row = __ldg(&ei[idx]);
    }
}

// ---------------- self-loop GEMM (initializes out) ----------------
__global__ void __launch_bounds__(256, 1)
k_self(float* __restrict__ out, int N) {
    extern __shared__ char dsm[];
    int tid = threadIdx.x;
    int wid = tid >> 5, lane = tid & 31;
    int e = tid & 127, half = tid >> 7;
    int n0 = blockIdx.x * TE;

    // stage B (w_self hi/lo)
    {
        const uint4* shi = (const uint4*)g_Shi;
        const uint4* slo = (const uint4*)g_Slo;
        uint4* dhi = (uint4*)(dsm + BOFS);
        uint4* dlo = (uint4*)(dsm + BOFS + PANEL_B);
#pragma unroll
        for (int i = tid; i < PANEL_B / 16; i += 256) {
            dhi[i] = shi[i];
            dlo[i] = slo[i];
        }
    }
    int n = n0 + e;
    issue_gather(dsm, ABUF(0), e, half, (n < N) ? n : -1);
    cp_commit();
    cp_wait0();
    __syncthreads();

    float acc[16][4];
    warp_mma(dsm, ABUF(0), wid, lane, acc);

    int ra = n0 + wid * 16 + (lane >> 2);
    int rb = ra + 8;
    int cb = (lane & 3) * 2;
#pragma unroll
    for (int t = 0; t < 16; t++) {
        if (ra < N) *(float2*)(out + (long long)ra * D + t * 8 + cb) = make_float2(acc[t][0], acc[t][1]);
        if (rb < N) *(float2*)(out + (long long)rb * D + t * 8 + cb) = make_float2(acc[t][2], acc[t][3]);
    }
}

// ---------------- persistent, double-buffered edge grouped GEMM ----------------
__global__ void __launch_bounds__(256, 1)
k_edge(const int* __restrict__ ei, float* __restrict__ out, int E) {
    __shared__ int s_toff[NREL + 1];
    __shared__ int s_off[NREL + 1];
    __shared__ int s_row[2][TE];
    __shared__ int s_tk;
    extern __shared__ char dsm[];

    int tid = threadIdx.x;
    int wid = tid >> 5, lane = tid & 31;
    int e = tid & 127, half = tid >> 7;

    if (tid < NREL + 1) {
        s_toff[tid] = g_tileoff[tid];
        s_off[tid]  = g_offsets[tid];
    }
    __syncthreads();
    int n_tiles = s_toff[NREL];

    // ---- prologue: tile t0 ----
    if (tid == 0) s_tk = atomicAdd(&g_ticket, 1);
    __syncthreads();
    int tc = s_tk;
    int rc, e0c, nec;
    resolve_tile(s_toff, s_off, tc, n_tiles, rc, e0c, nec);
    int colC, rowC;
    load_edge(ei, E, e0c, nec, e, colC, rowC);
    if (half == 0) s_row[0][e] = rowC;
    issue_gather(dsm, ABUF(0), e, half, colC);
    cp_commit();

    // ---- tile t1 indices ----
    if (tid == 0) s_tk = atomicAdd(&g_ticket, 1);
    __syncthreads();
    int tn = s_tk;
    int rn, e0n, nen;
    resolve_tile(s_toff, s_off, tn, n_tiles, rn, e0n, nen);
    int colN, rowN;
    load_edge(ei, E, e0n, nen, e, colN, rowN);

    int prev_r = -1, p = 0;

    while (tc < n_tiles) {
        if (tid == 0) s_tk = atomicAdd(&g_ticket, 1);
        cp_wait0();
        __syncthreads();                       // buf p ready; s_tk visible

        // issue next tile's gather into buf p^1 from pre-resolved registers
        if (half == 0) s_row[p ^ 1][e] = rowN;
        issue_gather(dsm, ABUF(p ^ 1), e, half, (tn < n_tiles) ? colN : -1);
        cp_commit();

        // resolve tile t+2 and kick off its index loads (hidden under MMA)
        int t2 = s_tk;
        int r2, e02, ne2;
        resolve_tile(s_toff, s_off, t2, n_tiles, r2, e02, ne2);
        int col2, row2;
        load_edge(ei, E, e02, ne2, e, col2, row2);

        // B panel for current relation (rare, uniform branch)
        if (rc != prev_r) {
            const uint4* shi = (const uint4*)(g_Bhi + rc * TILE_SH);
            const uint4* slo = (const uint4*)(g_Blo + rc * TILE_SH);
            uint4* dhi = (uint4*)(dsm + BOFS);
            uint4* dlo = (uint4*)(dsm + BOFS + PANEL_B);
#pragma unroll
            for (int i = tid; i < PANEL_B / 16; i += 256) {
                dhi[i] = shi[i];
                dlo[i] = slo[i];
            }
            prev_r = rc;
            __syncthreads();
        }

        float acc[16][4];
        warp_mma(dsm, ABUF(p), wid, lane, acc);

        int ra = s_row[p][wid * 16 + (lane >> 2)];
        int rb = s_row[p][wid * 16 + (lane >> 2) + 8];
        int cb = (lane & 3) * 2;
#pragma unroll
        for (int t = 0; t < 16; t++) {
            if (ra >= 0)
                atomicAdd((float2*)(out + (long long)ra * D + t * 8 + cb),
                          make_float2(acc[t][0], acc[t][1]));
            if (rb >= 0)
                atomicAdd((float2*)(out + (long long)rb * D + t * 8 + cb),
                          make_float2(acc[t][2], acc[t][3]));
        }

        // rotate pipeline state
        tc = tn; rc = rn;
        tn = t2; rn = r2; colN = col2; rowN = row2;
        p ^= 1;
    }
}

// ---------------- launcher ----------------
extern "C" void kernel_launch(void* const* d_in, const int* in_sizes, int n_in,
                              void* d_out, int out_size) {
    const float* x     = (const float*)d_in[0];
    const int*   ei    = (const int*)d_in[1];
    const int*   et    = (const int*)d_in[2];
    const float* bases = (const float*)d_in[3];
    const float* coeff = (const float*)d_in[4];
    const float* wself = (const float*)d_in[5];
    float* out = (float*)d_out;

    int N = in_sizes[0] / D;
    if (N > MAXN) N = MAXN;
    int E = in_sizes[2];
    if (E > MAXE) E = MAXE;

    int dev = 0, nsm = 148;
    cudaGetDevice(&dev);
    cudaDeviceGetAttribute(&nsm, cudaDevAttrMultiProcessorCount, dev);

    cudaFuncSetAttribute(k_self, cudaFuncAttributeMaxDynamicSharedMemorySize, SMEM_DYN);
    cudaFuncSetAttribute(k_edge, cudaFuncAttributeMaxDynamicSharedMemorySize, SMEM_DYN);

    int n4 = N * D / 4;
    k_xprep<<<(n4 + 255) / 256, 256>>>(x, n4);
    k_wprep<<<(NREL * D * D) / 256, 256>>>(bases, coeff);
    k_sprep<<<(D * D) / 256, 256>>>(wself);

    int gb = (E + 255) / 256;
    k_hist<<<gb, 256>>>(et, E);
    k_scan<<<1, 1>>>();
    k_perm<<<gb, 256>>>(et, E);

    k_self<<<(N + TE - 1) / TE, 256, SMEM_DYN>>>(out, N);
    k_edge<<<nsm, 256, SMEM_DYN>>>(ei, out, E);
}

// round 17
// speedup vs baseline: 3.2190x; 1.4220x over previous
#include <cuda_runtime.h>
#include <cuda_fp16.h>
#include <cstdint>

#define D     128
#define TE    128
#define NREL  16
#define NB    8
#define MAXE  600000
#define MAXN  100000

#define LDT   136                 // padded tile row, fp16 elems
#define LDTB  (LDT * 2)           // 272 bytes
#define TILE_SH (128 * LDT)       // ushorts per panel
#define PANEL_B (TILE_SH * 2)     // 34816 bytes

// dynamic smem: A double-buffered (single fp16 panel each), then B hi, B lo
#define ABUF(p) ((p) * PANEL_B)
#define BOFS    (2 * PANEL_B)
#define SMEM_DYN (4 * PANEL_B)    // 139264 B

// ---------------- device scratch ----------------
__device__ __align__(16) unsigned short g_xh[MAXN * D];        // x fp16
__device__ __align__(16) unsigned short g_Bhi[NREL * TILE_SH]; // W_r^T [o][k] fp16 hi
__device__ __align__(16) unsigned short g_Blo[NREL * TILE_SH]; // fp16 lo
__device__ __align__(16) unsigned short g_Shi[TILE_SH];        // w_self fp16 hi
__device__ __align__(16) unsigned short g_Slo[TILE_SH];
__device__ int g_counts[NREL];
__device__ int g_offsets[NREL + 1];
__device__ int g_cursor[NREL];
__device__ int g_tileoff[NREL + 1];
__device__ int g_perm[MAXE];

// ---------------- PTX helpers (baseline ISA only) ----------------
__device__ __forceinline__ uint32_t smem_u32(const void* p) {
    uint32_t a;
    asm("{ .reg .u64 t; cvta.to.shared.u64 t, %1; cvt.u32.u64 %0, t; }" : "=r"(a) : "l"(p));
    return a;
}
__device__ __forceinline__ void ldsm4(uint32_t* r, uint32_t addr) {
    asm volatile("ldmatrix.sync.aligned.m8n8.x4.shared.b16 {%0,%1,%2,%3}, [%4];"
                 : "=r"(r[0]), "=r"(r[1]), "=r"(r[2]), "=r"(r[3]) : "r"(addr));
}
__device__ __forceinline__ void mma16816(float* c, const uint32_t* a,
                                         uint32_t b0, uint32_t b1) {
    asm volatile(
        "mma.sync.aligned.m16n8k16.row.col.f32.f16.f16.f32 "
        "{%0,%1,%2,%3}, {%4,%5,%6,%7}, {%8,%9}, {%0,%1,%2,%3};"
        : "+f"(c[0]), "+f"(c[1]), "+f"(c[2]), "+f"(c[3])
        : "r"(a[0]), "r"(a[1]), "r"(a[2]), "r"(a[3]), "r"(b0), "r"(b1));
}
__device__ __forceinline__ uint32_t pk2h(float a, float b) {
    __half2 t = __floats2half2_rn(a, b);
    return *reinterpret_cast<uint32_t*>(&t);
}
__device__ __forceinline__ void cp16(uint32_t saddr, const void* gptr) {
    asm volatile("cp.async.cg.shared.global [%0], [%1], 16;"
                 :: "r"(saddr), "l"((uint64_t)__cvta_generic_to_global(gptr)) : "memory");
}
__device__ __forceinline__ void cp_commit() {
    asm volatile("cp.async.commit_group;" ::: "memory");
}
__device__ __forceinline__ void cp_wait0() {
    asm volatile("cp.async.wait_group 0;" ::: "memory");
}

// ---------------- prep kernels ----------------
__global__ void k_xprep(const float* __restrict__ x, int n4) {
    int g = blockIdx.x * blockDim.x + threadIdx.x;
    if (g >= n4) return;
    float4 v = ((const float4*)x)[g];
    ((uint2*)g_xh)[g] = make_uint2(pk2h(v.x, v.y), pk2h(v.z, v.w));
}

// g_B*[r][n=o][k=i] = fp16 hi/lo split of sum_b coeff[r][b]*bases[b][i][o]
__global__ void k_wprep(const float* __restrict__ bases,
                        const float* __restrict__ coeff) {
    int idx = blockIdx.x * blockDim.x + threadIdx.x;
    int r = idx >> 14;
    int n = (idx >> 7) & 127;
    int k = idx & 127;
    float s = 0.f;
#pragma unroll
    for (int b = 0; b < NB; b++)
        s = fmaf(__ldg(&coeff[r * NB + b]), __ldg(&bases[b * D * D + k * D + n]), s);
    __half hi = __float2half_rn(s);
    __half lo = __float2half_rn(s - __half2float(hi));
    int o = r * TILE_SH + n * LDT + k;
    g_Bhi[o] = *reinterpret_cast<unsigned short*>(&hi);
    g_Blo[o] = *reinterpret_cast<unsigned short*>(&lo);
}

__global__ void k_sprep(const float* __restrict__ w_self) {
    int idx = blockIdx.x * blockDim.x + threadIdx.x;
    if (idx < NREL) g_counts[idx] = 0;
    int n = idx >> 7, k = idx & 127;
    float s = w_self[n * D + k];
    __half hi = __float2half_rn(s);
    __half lo = __float2half_rn(s - __half2float(hi));
    g_Shi[n * LDT + k] = *reinterpret_cast<unsigned short*>(&hi);
    g_Slo[n * LDT + k] = *reinterpret_cast<unsigned short*>(&lo);
}

__global__ void k_hist(const int* __restrict__ etype, int E) {
    __shared__ int h[NREL];
    if (threadIdx.x < NREL) h[threadIdx.x] = 0;
    __syncthreads();
    int e = blockIdx.x * blockDim.x + threadIdx.x;
    if (e < E) atomicAdd(&h[etype[e] & (NREL - 1)], 1);
    __syncthreads();
    if (threadIdx.x < NREL && h[threadIdx.x])
        atomicAdd(&g_counts[threadIdx.x], h[threadIdx.x]);
}

__global__ void k_scan() {
    int off = 0, toff = 0;
    for (int r = 0; r < NREL; r++) {
        g_offsets[r] = off;
        g_cursor[r]  = off;
        g_tileoff[r] = toff;
        off  += g_counts[r];
        toff += (g_counts[r] + TE - 1) / TE;
    }
    g_offsets[NREL] = off;
    g_tileoff[NREL] = toff;
}

__global__ void k_perm(const int* __restrict__ etype, int E) {
    __shared__ int h[NREL];
    __shared__ int base[NREL];
    if (threadIdx.x < NREL) h[threadIdx.x] = 0;
    __syncthreads();
    int e = blockIdx.x * blockDim.x + threadIdx.x;
    int r = 0, loc = 0;
    bool valid = (e < E);
    if (valid) {
        r = etype[e] & (NREL - 1);
        loc = atomicAdd(&h[r], 1);
    }
    __syncthreads();
    if (threadIdx.x < NREL) {
        int c = h[threadIdx.x];
        base[threadIdx.x] = c ? atomicAdd(&g_cursor[threadIdx.x], c) : 0;
    }
    __syncthreads();
    if (valid) g_perm[base[r] + loc] = e;
}

// ---------------- warp-level mma core: acc = A_fp16 x (Bhi + Blo) ----------------
__device__ __forceinline__ void warp_mma(const char* dsm, int aofs, int wid, int lane,
                                         float acc[16][4]) {
#pragma unroll
    for (int t = 0; t < 16; t++)
#pragma unroll
        for (int q = 0; q < 4; q++) acc[t][q] = 0.f;

    uint32_t sA  = smem_u32(dsm + aofs);
    uint32_t sBh = smem_u32(dsm + BOFS);
    uint32_t sBl = sBh + PANEL_B;

    int m0 = wid * 16;
    uint32_t arow = (uint32_t)(m0 + (lane & 7) + 8 * ((lane >> 3) & 1)) * LDTB
                  + ((lane >> 4) << 4);

    uint32_t a[8][4];
#pragma unroll
    for (int k = 0; k < 8; k++) ldsm4(a[k], sA + arow + k * 32);

    int g = lane >> 3, rr = lane & 7;
    uint32_t brow = (uint32_t)(((g >> 1) * 8 + rr)) * LDTB + (uint32_t)((g & 1) << 4);

#pragma unroll
    for (int p = 0; p < 8; p++) {
        uint32_t bph = sBh + (uint32_t)(p * 16) * LDTB + brow;
        uint32_t bpl = sBl + (uint32_t)(p * 16) * LDTB + brow;
#pragma unroll
        for (int k = 0; k < 8; k++) {
            uint32_t bh[4], bl[4];
            ldsm4(bh, bph + k * 32);
            ldsm4(bl, bpl + k * 32);
            mma16816(acc[2 * p],     a[k], bh[0], bh[1]);
            mma16816(acc[2 * p],     a[k], bl[0], bl[1]);
            mma16816(acc[2 * p + 1], a[k], bh[2], bh[3]);
            mma16816(acc[2 * p + 1], a[k], bl[2], bl[3]);
        }
    }
}

// async copy of one edge-row half (64 fp16 = 128 BYTES -> 8 x cp16).
// col < 0: zero-fill the half-row so no garbage ever enters the MMA.
__device__ __forceinline__ void issue_gather(char* dsm, int bufofs, int e, int half, int col) {
    char* drow = dsm + bufofs + e * LDTB + half * 128;
    if (col < 0) {
        uint4 z = make_uint4(0u, 0u, 0u, 0u);
#pragma unroll
        for (int j = 0; j < 8; j++) *(uint4*)(drow + j * 16) = z;
        return;
    }
    const unsigned short* s = g_xh + (long long)col * D + half * 64;
    uint32_t d = smem_u32(drow);
#pragma unroll
    for (int j = 0; j < 8; j++) cp16(d + j * 16, s + j * 8);
}

__device__ __forceinline__ void resolve_tile(const int* s_toff, const int* s_off,
                                             int t, int n_tiles,
                                             int& r, int& e0, int& ne) {
    r = 0; e0 = 0; ne = 0;
    if (t >= n_tiles) return;
#pragma unroll
    for (int i = 1; i < NREL; i++) if (s_toff[i] <= t) r = i;
    e0 = s_off[r] + (t - s_toff[r]) * TE;
    ne = min(s_off[r + 1] - e0, TE);
}

__device__ __forceinline__ void load_edge(const int* __restrict__ ei, int E,
                                          int e0, int ne, int e,
                                          int& col, int& row) {
    col = -1; row = -1;
    if (e < ne) {
        int idx = __ldg(&g_perm[e0 + e]);
        col = __ldg(&ei[E + idx]);
        row = __ldg(&ei[idx]);
    }
}

// ---------------- self-loop GEMM (initializes out) ----------------
__global__ void __launch_bounds__(256, 1)
k_self(float* __restrict__ out, int N) {
    extern __shared__ char dsm[];
    int tid = threadIdx.x;
    int wid = tid >> 5, lane = tid & 31;
    int e = tid & 127, half = tid >> 7;
    int n0 = blockIdx.x * TE;

    {
        const uint4* shi = (const uint4*)g_Shi;
        const uint4* slo = (const uint4*)g_Slo;
        uint4* dhi = (uint4*)(dsm + BOFS);
        uint4* dlo = (uint4*)(dsm + BOFS + PANEL_B);
#pragma unroll
        for (int i = tid; i < PANEL_B / 16; i += 256) {
            dhi[i] = shi[i];
            dlo[i] = slo[i];
        }
    }
    int n = n0 + e;
    issue_gather(dsm, ABUF(0), e, half, (n < N) ? n : -1);
    cp_commit();
    cp_wait0();
    __syncthreads();

    float acc[16][4];
    warp_mma(dsm, ABUF(0), wid, lane, acc);

    int ra = n0 + wid * 16 + (lane >> 2);
    int rb = ra + 8;
    int cb = (lane & 3) * 2;
#pragma unroll
    for (int t = 0; t < 16; t++) {
        if (ra < N) *(float2*)(out + (long long)ra * D + t * 8 + cb) = make_float2(acc[t][0], acc[t][1]);
        if (rb < N) *(float2*)(out + (long long)rb * D + t * 8 + cb) = make_float2(acc[t][2], acc[t][3]);
    }
}

// ---------------- edge grouped GEMM: static contiguous tile ranges ----------------
__global__ void __launch_bounds__(256, 1)
k_edge(const int* __restrict__ ei, float* __restrict__ out, int E) {
    __shared__ int s_toff[NREL + 1];
    __shared__ int s_off[NREL + 1];
    __shared__ int s_row[2][TE];
    extern __shared__ char dsm[];

    int tid = threadIdx.x;
    int wid = tid >> 5, lane = tid & 31;
    int e = tid & 127, half = tid >> 7;

    if (tid < NREL + 1) {
        s_toff[tid] = g_tileoff[tid];
        s_off[tid]  = g_offsets[tid];
    }
    __syncthreads();
    int n_tiles = s_toff[NREL];
    int tpc = (n_tiles + gridDim.x - 1) / gridDim.x;
    int t0 = blockIdx.x * tpc;
    int t1 = min(t0 + tpc, n_tiles);
    if (t0 >= n_tiles) return;

    // prologue: tile t0
    int rc, e0c, nec;
    resolve_tile(s_toff, s_off, t0, n_tiles, rc, e0c, nec);
    int colC, rowC;
    load_edge(ei, E, e0c, nec, e, colC, rowC);
    if (half == 0) s_row[0][e] = rowC;
    issue_gather(dsm, ABUF(0), e, half, colC);
    cp_commit();

    // tile t0+1 indices
    int rn = 0, colN = -1, rowN = -1;
    if (t0 + 1 < t1) {
        int e0n, nen;
        resolve_tile(s_toff, s_off, t0 + 1, n_tiles, rn, e0n, nen);
        load_edge(ei, E, e0n, nen, e, colN, rowN);
    }

    int prev_r = -1, p = 0;

    for (int t = t0; t < t1; t++) {
        cp_wait0();
        __syncthreads();                       // buf p ready; prev epilogue done

        if (half == 0) s_row[p ^ 1][e] = rowN;
        issue_gather(dsm, ABUF(p ^ 1), e, half, colN);
        cp_commit();

        // resolve t+2 (L2 latency hides under the MMA)
        int r2 = 0, col2 = -1, row2 = -1;
        if (t + 2 < t1) {
            int e02, ne2;
            resolve_tile(s_toff, s_off, t + 2, n_tiles, r2, e02, ne2);
            load_edge(ei, E, e02, ne2, e, col2, row2);
        }

        // B panels (contiguous range -> rare, ~1-2 reloads per CTA)
        if (rc != prev_r) {
            const uint4* shi = (const uint4*)(g_Bhi + rc * TILE_SH);
            const uint4* slo = (const uint4*)(g_Blo + rc * TILE_SH);
            uint4* dhi = (uint4*)(dsm + BOFS);
            uint4* dlo = (uint4*)(dsm + BOFS + PANEL_B);
#pragma unroll
            for (int i = tid; i < PANEL_B / 16; i += 256) {
                dhi[i] = shi[i];
                dlo[i] = slo[i];
            }
            prev_r = rc;
            __syncthreads();
        }

        float acc[16][4];
        warp_mma(dsm, ABUF(p), wid, lane, acc);

        int ra = s_row[p][wid * 16 + (lane >> 2)];
        int rb = s_row[p][wid * 16 + (lane >> 2) + 8];
        int cb = (lane & 3) * 2;
#pragma unroll
        for (int q = 0; q < 16; q++) {
            if (ra >= 0)
                atomicAdd((float2*)(out + (long long)ra * D + q * 8 + cb),
                          make_float2(acc[q][0], acc[q][1]));
            if (rb >= 0)
                atomicAdd((float2*)(out + (long long)rb * D + q * 8 + cb),
                          make_float2(acc[q][2], acc[q][3]));
        }

        rc = rn; rn = r2; colN = col2; rowN = row2;
        p ^= 1;
    }
}

// ---------------- launcher ----------------
extern "C" void kernel_launch(void* const* d_in, const int* in_sizes, int n_in,
                              void* d_out, int out_size) {
    const float* x     = (const float*)d_in[0];
    const int*   ei    = (const int*)d_in[1];
    const int*   et    = (const int*)d_in[2];
    const float* bases = (const float*)d_in[3];
    const float* coeff = (const float*)d_in[4];
    const float* wself = (const float*)d_in[5];
    float* out = (float*)d_out;

    int N = in_sizes[0] / D;
    if (N > MAXN) N = MAXN;
    int E = in_sizes[2];
    if (E > MAXE) E = MAXE;

    int dev = 0, nsm = 148;
    cudaGetDevice(&dev);
    cudaDeviceGetAttribute(&nsm, cudaDevAttrMultiProcessorCount, dev);

    cudaFuncSetAttribute(k_self, cudaFuncAttributeMaxDynamicSharedMemorySize, SMEM_DYN);
    cudaFuncSetAttribute(k_edge, cudaFuncAttributeMaxDynamicSharedMemorySize, SMEM_DYN);

    int n4 = N * D / 4;
    k_xprep<<<(n4 + 255) / 256, 256>>>(x, n4);
    k_wprep<<<(NREL * D * D) / 256, 256>>>(bases, coeff);
    k_sprep<<<(D * D) / 256, 256>>>(wself);

    int gb = (E + 255) / 256;
    k_hist<<<gb, 256>>>(et, E);
    k_scan<<<1, 1>>>();
    k_perm<<<gb, 256>>>(et, E);

    k_self<<<(N + TE - 1) / TE, 256, SMEM_DYN>>>(out, N);
    k_edge<<<nsm, 256, SMEM_DYN>>>(ei, out, E);
}